// round 2
// baseline (speedup 1.0000x reference)
#include <cuda_runtime.h>

#define B_ 8
#define N_ 2000
#define F_ 128
#define K_ 64

// -------- device scratch (no allocations allowed) --------
__device__ float g_P[B_*N_*K_];       // masked softmax(s)  [b,n,k]
__device__ float g_AS[B_*N_*K_];      // adj @ P            [b,n,k]
__device__ float g_Q[B_*N_];          // sum_k P^2          [b,n]
__device__ float g_D[B_*N_];          // rowsum adj         [b,n]
__device__ float g_OUTADJ[B_*K_*K_];  // raw S^T A^T S
__device__ float g_SS[B_*K_*K_];      // P^T P
__device__ float g_DEN[B_];
__device__ float g_LOSS[2*B_];

// -------- init: zero accumulators + out region of d_out --------
__global__ void k_init(float* __restrict__ out_region) {
    int i = blockIdx.x * blockDim.x + threadIdx.x;
    if (i < B_*K_*F_) out_region[i] = 0.f;       // 65536
    if (i < B_*K_*K_) { g_OUTADJ[i] = 0.f; g_SS[i] = 0.f; }
    if (i < B_) g_DEN[i] = 0.f;
}

// -------- softmax over K=64, one warp per row --------
__global__ void k_softmax(const float* __restrict__ s,
                          const int* __restrict__ mask) {   // bool -> int32
    int row = (blockIdx.x * blockDim.x + threadIdx.x) >> 5;  // b*N+n
    if (row >= B_*N_) return;
    int lane = threadIdx.x & 31;
    const float* sr = s + (size_t)row * K_;
    float v0 = sr[lane], v1 = sr[lane + 32];
    float mx = fmaxf(v0, v1);
    #pragma unroll
    for (int o = 16; o; o >>= 1) mx = fmaxf(mx, __shfl_xor_sync(0xffffffffu, mx, o));
    float e0 = expf(v0 - mx), e1 = expf(v1 - mx);
    float sm = e0 + e1;
    #pragma unroll
    for (int o = 16; o; o >>= 1) sm += __shfl_xor_sync(0xffffffffu, sm, o);
    float m = (mask[row] != 0) ? 1.f : 0.f;
    float inv = m / sm;
    float p0 = e0 * inv, p1 = e1 * inv;
    g_P[(size_t)row * K_ + lane]      = p0;
    g_P[(size_t)row * K_ + lane + 32] = p1;
    float q = p0 * p0 + p1 * p1;
    #pragma unroll
    for (int o = 16; o; o >>= 1) q += __shfl_xor_sync(0xffffffffu, q, o);
    if (lane == 0) g_Q[row] = q;
}

// -------- out[b,k,f] = sum_n P[b,n,k] * x[b,n,f]  (mask folded into P) --------
__global__ void __launch_bounds__(256) k_out_gemm(const float* __restrict__ x,
                                                  float* __restrict__ out) {
    int b = blockIdx.y;
    int row0 = blockIdx.x * 128;
    int rows = min(128, N_ - row0);
    __shared__ float Ps[32][64];
    __shared__ float Xs[32][128];
    int tid = threadIdx.x;
    int kq = tid & 15;    // 16 k-groups * 4
    int fq = tid >> 4;    // 16 f-groups * 8
    float acc[4][8] = {};
    const float* Pb = g_P + (size_t)b * N_ * K_ + (size_t)row0 * K_;
    const float* Xb = x   + (size_t)b * N_ * F_ + (size_t)row0 * F_;
    for (int t0 = 0; t0 < rows; t0 += 32) {
        #pragma unroll
        for (int i = 0; i < 8; i++) {
            int idx = tid + i * 256;
            int r = idx >> 6, c = idx & 63;
            Ps[r][c] = (t0 + r < rows) ? Pb[(size_t)(t0 + r) * K_ + c] : 0.f;
        }
        #pragma unroll
        for (int i = 0; i < 16; i++) {
            int idx = tid + i * 256;
            int r = idx >> 7, c = idx & 127;
            Xs[r][c] = (t0 + r < rows) ? Xb[(size_t)(t0 + r) * F_ + c] : 0.f;
        }
        __syncthreads();
        #pragma unroll 8
        for (int m = 0; m < 32; m++) {
            float4 pv  = *(const float4*)&Ps[m][kq * 4];
            float4 xv0 = *(const float4*)&Xs[m][fq * 8];
            float4 xv1 = *(const float4*)&Xs[m][fq * 8 + 4];
            float a[4]  = {pv.x, pv.y, pv.z, pv.w};
            float bb[8] = {xv0.x, xv0.y, xv0.z, xv0.w, xv1.x, xv1.y, xv1.z, xv1.w};
            #pragma unroll
            for (int i = 0; i < 4; i++)
                #pragma unroll
                for (int j = 0; j < 8; j++)
                    acc[i][j] = fmaf(a[i], bb[j], acc[i][j]);
        }
        __syncthreads();
    }
    float* ob = out + (size_t)b * K_ * F_;
    #pragma unroll
    for (int i = 0; i < 4; i++)
        #pragma unroll
        for (int j = 0; j < 8; j++)
            atomicAdd(&ob[(kq * 4 + i) * F_ + fq * 8 + j], acc[i][j]);
}

// -------- AS = adj @ P  (+ fused degree rowsum).  Tile 128x64, TM=32 --------
__global__ void __launch_bounds__(256) k_adj_gemm(const float* __restrict__ adj) {
    int b = blockIdx.y;
    int row0 = blockIdx.x * 128;
    int rows = min(128, N_ - row0);
    __shared__ float As[32][132];   // [m][row], pad 132 for conflict-free
    __shared__ float Ps[32][64];
    int tid = threadIdx.x;
    int rg = tid & 31;   // 32 row-groups * 4 rows
    int cg = tid >> 5;   // 8 col-groups * 8 cols
    float acc[4][8] = {};
    float dsum = 0.f;
    const float* Ab = adj + (size_t)b * N_ * N_;
    const float* Pb = g_P + (size_t)b * N_ * K_;

    for (int m0 = 0; m0 < N_; m0 += 32) {
        // adj tile 128x32 -> transposed smem. coalesced gmem float4 reads.
        #pragma unroll
        for (int l = 0; l < 4; l++) {
            int lin = tid + l * 256;          // 0..1023
            int mg = lin & 7;                 // 8 m-groups of 4
            int r  = lin >> 3;                // 0..127
            float4 v = make_float4(0.f, 0.f, 0.f, 0.f);
            int gm = m0 + mg * 4;
            if (r < rows && gm < N_)          // N_%4==0 -> never straddles
                v = *(const float4*)&Ab[(size_t)(row0 + r) * N_ + gm];
            As[mg * 4 + 0][r] = v.x;
            As[mg * 4 + 1][r] = v.y;
            As[mg * 4 + 2][r] = v.z;
            As[mg * 4 + 3][r] = v.w;
        }
        #pragma unroll
        for (int i = 0; i < 8; i++) {
            int idx = tid + i * 256;
            int r = idx >> 6, c = idx & 63;
            Ps[r][c] = (m0 + r < N_) ? Pb[(size_t)(m0 + r) * K_ + c] : 0.f;
        }
        __syncthreads();

        if (tid < 128) {                      // degree rowsum (zero-padded safe)
            float s = 0.f;
            #pragma unroll
            for (int m = 0; m < 32; m++) s += As[m][tid];
            dsum += s;
        }
        #pragma unroll 8
        for (int m = 0; m < 32; m++) {
            float4 av = *(const float4*)&As[m][rg * 4];
            float4 b0 = *(const float4*)&Ps[m][cg * 8];
            float4 b1 = *(const float4*)&Ps[m][cg * 8 + 4];
            float a[4]  = {av.x, av.y, av.z, av.w};
            float bb[8] = {b0.x, b0.y, b0.z, b0.w, b1.x, b1.y, b1.z, b1.w};
            #pragma unroll
            for (int i = 0; i < 4; i++)
                #pragma unroll
                for (int j = 0; j < 8; j++)
                    acc[i][j] = fmaf(a[i], bb[j], acc[i][j]);
        }
        __syncthreads();
    }

    float* ASb = g_AS + (size_t)b * N_ * K_;
    #pragma unroll
    for (int i = 0; i < 4; i++) {
        int r = rg * 4 + i;
        if (r < rows)
            #pragma unroll
            for (int j = 0; j < 8; j++)
                ASb[(size_t)(row0 + r) * K_ + cg * 8 + j] = acc[i][j];
    }
    if (tid < 128 && tid < rows) g_D[b * N_ + row0 + tid] = dsum;
}

// -------- out_adj = AS^T P, ss = P^T P, den = sum d*q --------
__global__ void __launch_bounds__(256) k_small(void) {
    int b = blockIdx.y;
    int n0 = blockIdx.x * 250;
    __shared__ float ASs[16][64];
    __shared__ float Ps[16][64];
    __shared__ float red[256];
    int tid = threadIdx.x;
    int kg = tid & 15;   // 16 groups * 4 k
    int lg = tid >> 4;   // 16 groups * 4 l
    float accA[4][4] = {};
    float accS[4][4] = {};
    const float* ASb = g_AS + (size_t)b * N_ * K_;
    const float* Pb  = g_P  + (size_t)b * N_ * K_;
    for (int t0 = 0; t0 < 250; t0 += 16) {
        #pragma unroll
        for (int i = 0; i < 4; i++) {
            int idx = tid + i * 256;
            int r = idx >> 6, c = idx & 63;
            bool ok = (t0 + r) < 250;
            size_t g = (size_t)(n0 + t0 + r) * K_ + c;
            ASs[r][c] = ok ? ASb[g] : 0.f;
            Ps[r][c]  = ok ? Pb[g]  : 0.f;
        }
        __syncthreads();
        #pragma unroll 8
        for (int m = 0; m < 16; m++) {
            float4 ak = *(const float4*)&ASs[m][kg * 4];
            float4 pk = *(const float4*)&Ps[m][kg * 4];
            float4 pl = *(const float4*)&Ps[m][lg * 4];
            float a[4] = {ak.x, ak.y, ak.z, ak.w};
            float p[4] = {pk.x, pk.y, pk.z, pk.w};
            float q[4] = {pl.x, pl.y, pl.z, pl.w};
            #pragma unroll
            for (int i = 0; i < 4; i++)
                #pragma unroll
                for (int j = 0; j < 4; j++) {
                    accA[i][j] = fmaf(a[i], q[j], accA[i][j]);
                    accS[i][j] = fmaf(p[i], q[j], accS[i][j]);
                }
        }
        __syncthreads();
    }
    float* OA  = g_OUTADJ + b * K_ * K_;
    float* SSb = g_SS     + b * K_ * K_;
    #pragma unroll
    for (int i = 0; i < 4; i++)
        #pragma unroll
        for (int j = 0; j < 4; j++) {
            atomicAdd(&OA [(kg * 4 + i) * K_ + lg * 4 + j], accA[i][j]);
            atomicAdd(&SSb[(kg * 4 + i) * K_ + lg * 4 + j], accS[i][j]);
        }
    // den partial
    float dq = 0.f;
    for (int n = tid; n < 250; n += 256) {
        int gi = b * N_ + n0 + n;
        dq += g_D[gi] * g_Q[gi];
    }
    red[tid] = dq; __syncthreads();
    for (int st = 128; st; st >>= 1) { if (tid < st) red[tid] += red[tid + st]; __syncthreads(); }
    if (tid == 0) atomicAdd(&g_DEN[b], red[0]);
}

// -------- per-batch finalize: losses + normalized out_adj --------
__global__ void k_finalize(float* __restrict__ outadj_out) {
    int b = blockIdx.x;
    int tid = threadIdx.x;
    const float* OA  = g_OUTADJ + b * K_ * K_;
    const float* SSb = g_SS     + b * K_ * K_;
    __shared__ float red[256];
    __shared__ float s_frob, s_trace;
    __shared__ float dvec[K_];

    // ||ss||_F
    float fs = 0.f;
    for (int i = tid; i < K_*K_; i += 256) { float v = SSb[i]; fs += v * v; }
    red[tid] = fs; __syncthreads();
    for (int st = 128; st; st >>= 1) { if (tid < st) red[tid] += red[tid + st]; __syncthreads(); }
    if (tid == 0) s_frob = sqrtf(red[0]);
    __syncthreads();
    float frob = s_frob;

    // ortho = || ss/frob - I/8 ||_F
    float os = 0.f;
    for (int i = tid; i < K_*K_; i += 256) {
        int k = i >> 6, l = i & 63;
        float v = SSb[i] / frob - ((k == l) ? 0.125f : 0.f);
        os += v * v;
    }
    red[tid] = os; __syncthreads();
    for (int st = 128; st; st >>= 1) { if (tid < st) red[tid] += red[tid + st]; __syncthreads(); }
    float ortho = sqrtf(red[0]);
    __syncthreads();

    // trace (of raw out_adj, before diag zeroing)
    float tr = (tid < K_) ? OA[tid * K_ + tid] : 0.f;
    red[tid] = tr; __syncthreads();
    for (int st = 128; st; st >>= 1) { if (tid < st) red[tid] += red[tid + st]; __syncthreads(); }
    if (tid == 0) s_trace = red[0];
    __syncthreads();

    // row sums with zeroed diag -> degree norm
    if (tid < K_) {
        float rs = 0.f;
        #pragma unroll
        for (int l = 0; l < K_; l++) if (l != tid) rs += OA[tid * K_ + l];
        dvec[tid] = sqrtf(rs) + 1e-15f;
    }
    __syncthreads();
    for (int i = tid; i < K_*K_; i += 256) {
        int k = i >> 6, l = i & 63;
        float v = (k == l) ? 0.f : OA[i] / (dvec[k] * dvec[l]);
        outadj_out[b * K_ * K_ + i] = v;
    }
    if (tid == 0) {
        g_LOSS[b]      = -(s_trace / g_DEN[b]);
        g_LOSS[B_ + b] = ortho;
    }
}

__global__ void k_losses(float* __restrict__ out2) {
    if (threadIdx.x == 0) {
        float a = 0.f, o = 0.f;
        #pragma unroll
        for (int b = 0; b < B_; b++) { a += g_LOSS[b]; o += g_LOSS[B_ + b]; }
        out2[0] = a * (1.f / B_);
        out2[1] = o * (1.f / B_);
    }
}

extern "C" void kernel_launch(void* const* d_in, const int* in_sizes, int n_in,
                              void* d_out, int out_size) {
    const float* x   = (const float*)d_in[0];          // [8,2000,128] f32
    const float* adj = (const float*)d_in[1];          // [8,2000,2000] f32
    const float* s   = (const float*)d_in[2];          // [8,2000,64] f32
    const int*   mask = (const int*)d_in[3];           // [8,2000] bool -> int32
    float* out = (float*)d_out;
    // layout: out [8,64,128] | out_adj [8,64,64] | mincut_loss | ortho_loss

    k_init<<<256, 256>>>(out);
    k_softmax<<<(B_*N_*32 + 255) / 256, 256>>>(s, mask);
    dim3 g2(16, B_); k_out_gemm<<<g2, 256>>>(x, out);
    dim3 g3(16, B_); k_adj_gemm<<<g3, 256>>>(adj);
    dim3 g4(8, B_);  k_small<<<g4, 256>>>();
    k_finalize<<<B_, 256>>>(out + B_*K_*F_);
    k_losses<<<1, 32>>>(out + B_*K_*F_ + B_*K_*K_);
    (void)in_sizes; (void)n_in; (void)out_size;
}